// round 4
// baseline (speedup 1.0000x reference)
#include <cuda_runtime.h>
#include <cstdint>
#include <cstddef>

#define BB 4
#define SS 2048
#define DM 1024
#define NH 16
#define DK 64
#define BH (BB*NH)

#define TS 64
#define KC 16
#define PAD 4   // smem row padding

// Scratch (allocation-free rule: __device__ globals)
__device__ float g_Q[BB*NH*SS*DK];   // [b,h,s,d]
__device__ float g_K[BB*NH*SS*DK];
__device__ float g_V[BB*NH*SS*DK];
__device__ float g_AO[BB*SS*DM];     // [b,s,h*64+d]

// ---------------------------------------------------------------------------
// Kernel 1: QKV projections. C[i][j] = sum_k X[i][k]*W[j][k] + b[j]
// Writes into g_Q/g_K/g_V in [b,h,s,d] layout.
// grid: (DM/TS, (BB*SS)/TS, 3), block: 256
// ---------------------------------------------------------------------------
__global__ __launch_bounds__(256) void proj_qkv_kernel(
    const float* __restrict__ Xq, const float* __restrict__ Xk, const float* __restrict__ Xv,
    const float* __restrict__ Wq, const float* __restrict__ bq,
    const float* __restrict__ Wk, const float* __restrict__ bk,
    const float* __restrict__ Wv, const float* __restrict__ bv)
{
    __shared__ float As[KC][TS+PAD];
    __shared__ float Bs[KC][TS+PAD];

    int which = blockIdx.z;
    const float* X    = (which==0) ? Xq : (which==1 ? Xk : Xv);
    const float* W    = (which==0) ? Wq : (which==1 ? Wk : Wv);
    const float* bias = (which==0) ? bq : (which==1 ? bk : bv);
    float* dst        = (which==0) ? g_Q : (which==1 ? g_K : g_V);

    int tid = threadIdx.x;
    int tx = tid & 15, ty = tid >> 4;
    int rowBase = blockIdx.y * TS;
    int colBase = blockIdx.x * TS;
    int lrow = tid >> 2, lkq = tid & 3;

    float acc[4][4] = {};

    for (int kc = 0; kc < DM; kc += KC) {
        float4 av  = *(const float4*)(X + (size_t)(rowBase + lrow) * DM + kc + lkq * 4);
        float4 bv4 = *(const float4*)(W + (size_t)(colBase + lrow) * DM + kc + lkq * 4);
        As[lkq*4+0][lrow] = av.x;  As[lkq*4+1][lrow] = av.y;
        As[lkq*4+2][lrow] = av.z;  As[lkq*4+3][lrow] = av.w;
        Bs[lkq*4+0][lrow] = bv4.x; Bs[lkq*4+1][lrow] = bv4.y;
        Bs[lkq*4+2][lrow] = bv4.z; Bs[lkq*4+3][lrow] = bv4.w;
        __syncthreads();

        #pragma unroll
        for (int k = 0; k < KC; k++) {
            float4 a = *(const float4*)&As[k][ty*4];
            float4 b = *(const float4*)&Bs[k][tx*4];
            float ar[4] = {a.x, a.y, a.z, a.w};
            float br[4] = {b.x, b.y, b.z, b.w};
            #pragma unroll
            for (int r = 0; r < 4; r++)
                #pragma unroll
                for (int c = 0; c < 4; c++)
                    acc[r][c] += ar[r] * br[c];
        }
        __syncthreads();
    }

    #pragma unroll
    for (int r = 0; r < 4; r++) {
        int gi = rowBase + ty*4 + r;
        int b_idx = gi >> 11;            // / SS
        int s_idx = gi & (SS - 1);
        #pragma unroll
        for (int c = 0; c < 4; c++) {
            int gj = colBase + tx*4 + c;
            int h_idx = gj >> 6;
            int d_idx = gj & 63;
            float v = acc[r][c] + bias[gj];
            dst[(((size_t)(b_idx*NH + h_idx))*SS + s_idx)*DK + d_idx] = v;
        }
    }
}

// ---------------------------------------------------------------------------
// Kernel 2: scores = Q K^T / 8 per (b,h).  Writes raw scores into attn buffer.
// grid: (SS/TS, SS/TS, BH), block: 256
// ---------------------------------------------------------------------------
__global__ __launch_bounds__(256) void scores_kernel(float* __restrict__ attn)
{
    __shared__ float As[KC][TS+PAD];
    __shared__ float Bs[KC][TS+PAD];

    int bh = blockIdx.z;
    const float* Qh = g_Q + (size_t)bh * SS * DK;
    const float* Kh = g_K + (size_t)bh * SS * DK;

    int tid = threadIdx.x;
    int tx = tid & 15, ty = tid >> 4;
    int rowBase = blockIdx.y * TS;
    int colBase = blockIdx.x * TS;
    int lrow = tid >> 2, lkq = tid & 3;

    float acc[4][4] = {};

    for (int kc = 0; kc < DK; kc += KC) {
        float4 av  = *(const float4*)(Qh + (size_t)(rowBase + lrow) * DK + kc + lkq * 4);
        float4 bv4 = *(const float4*)(Kh + (size_t)(colBase + lrow) * DK + kc + lkq * 4);
        As[lkq*4+0][lrow] = av.x;  As[lkq*4+1][lrow] = av.y;
        As[lkq*4+2][lrow] = av.z;  As[lkq*4+3][lrow] = av.w;
        Bs[lkq*4+0][lrow] = bv4.x; Bs[lkq*4+1][lrow] = bv4.y;
        Bs[lkq*4+2][lrow] = bv4.z; Bs[lkq*4+3][lrow] = bv4.w;
        __syncthreads();

        #pragma unroll
        for (int k = 0; k < KC; k++) {
            float4 a = *(const float4*)&As[k][ty*4];
            float4 b = *(const float4*)&Bs[k][tx*4];
            float ar[4] = {a.x, a.y, a.z, a.w};
            float br[4] = {b.x, b.y, b.z, b.w};
            #pragma unroll
            for (int r = 0; r < 4; r++)
                #pragma unroll
                for (int c = 0; c < 4; c++)
                    acc[r][c] += ar[r] * br[c];
        }
        __syncthreads();
    }

    float* base = attn + (size_t)bh * SS * SS;
    #pragma unroll
    for (int r = 0; r < 4; r++) {
        int gi = rowBase + ty*4 + r;
        #pragma unroll
        for (int c = 0; c < 4; c++) {
            int gj = colBase + tx*4 + c;
            base[(size_t)gi * SS + gj] = acc[r][c] * 0.125f;
        }
    }
}

// ---------------------------------------------------------------------------
// Kernel 3: in-place row softmax. One block (256 thr) per row of 2048.
// grid: BH*SS, block: 256
// ---------------------------------------------------------------------------
__global__ __launch_bounds__(256) void softmax_kernel(float* __restrict__ attn)
{
    __shared__ float sh[256];
    float* p = attn + (size_t)blockIdx.x * SS;
    int tid = threadIdx.x;

    float v[8];
    float4 a0 = *(const float4*)(p + tid*8);
    float4 a1 = *(const float4*)(p + tid*8 + 4);
    v[0]=a0.x; v[1]=a0.y; v[2]=a0.z; v[3]=a0.w;
    v[4]=a1.x; v[5]=a1.y; v[6]=a1.z; v[7]=a1.w;

    float m = v[0];
    #pragma unroll
    for (int i = 1; i < 8; i++) m = fmaxf(m, v[i]);
    sh[tid] = m;
    __syncthreads();
    for (int s = 128; s > 0; s >>= 1) {
        if (tid < s) sh[tid] = fmaxf(sh[tid], sh[tid + s]);
        __syncthreads();
    }
    m = sh[0];
    __syncthreads();

    float lsum = 0.0f;
    #pragma unroll
    for (int i = 0; i < 8; i++) { v[i] = expf(v[i] - m); lsum += v[i]; }
    sh[tid] = lsum;
    __syncthreads();
    for (int s = 128; s > 0; s >>= 1) {
        if (tid < s) sh[tid] = sh[tid] + sh[tid + s];
        __syncthreads();
    }
    float inv = 1.0f / sh[0];

    float4 o0 = make_float4(v[0]*inv, v[1]*inv, v[2]*inv, v[3]*inv);
    float4 o1 = make_float4(v[4]*inv, v[5]*inv, v[6]*inv, v[7]*inv);
    *(float4*)(p + tid*8)     = o0;
    *(float4*)(p + tid*8 + 4) = o1;
}

// ---------------------------------------------------------------------------
// Kernel 4: attn_output = attn @ V per (b,h).  M=2048, N=64, K=2048.
// Writes into g_AO in [b,s,h*64+d] layout.
// grid: (SS/TS, 1, BH), block: 256
// ---------------------------------------------------------------------------
__global__ __launch_bounds__(256) void av_kernel(const float* __restrict__ attn)
{
    __shared__ float As[KC][TS+PAD];
    __shared__ float Bs[KC][TS+PAD];

    int bh = blockIdx.z;
    const float* Wrow = attn + (size_t)bh * SS * SS;
    const float* Vh   = g_V + (size_t)bh * SS * DK;

    int tid = threadIdx.x;
    int tx = tid & 15, ty = tid >> 4;
    int rowBase = blockIdx.x * TS;
    int lrow = tid >> 2, lkq = tid & 3;   // for A
    int lc = tid >> 4, ldq = tid & 15;    // for B (direct)

    float acc[4][4] = {};

    for (int kc = 0; kc < SS; kc += KC) {
        float4 av = *(const float4*)(Wrow + (size_t)(rowBase + lrow) * SS + kc + lkq * 4);
        As[lkq*4+0][lrow] = av.x;  As[lkq*4+1][lrow] = av.y;
        As[lkq*4+2][lrow] = av.z;  As[lkq*4+3][lrow] = av.w;
        float4 bv4 = *(const float4*)(Vh + (size_t)(kc + lc) * DK + ldq * 4);
        *(float4*)&Bs[lc][ldq*4] = bv4;
        __syncthreads();

        #pragma unroll
        for (int k = 0; k < KC; k++) {
            float4 a = *(const float4*)&As[k][ty*4];
            float4 b = *(const float4*)&Bs[k][tx*4];
            float ar[4] = {a.x, a.y, a.z, a.w};
            float br[4] = {b.x, b.y, b.z, b.w};
            #pragma unroll
            for (int r = 0; r < 4; r++)
                #pragma unroll
                for (int c = 0; c < 4; c++)
                    acc[r][c] += ar[r] * br[c];
        }
        __syncthreads();
    }

    int b_idx = bh >> 4;
    int h_idx = bh & 15;
    #pragma unroll
    for (int r = 0; r < 4; r++) {
        int gi = rowBase + ty*4 + r;   // s index
        #pragma unroll
        for (int c = 0; c < 4; c++) {
            int gj = tx*4 + c;         // d index
            g_AO[((size_t)b_idx*SS + gi)*DM + h_idx*DK + gj] = acc[r][c];
        }
    }
}

// ---------------------------------------------------------------------------
// Kernel 5: output projection. out = g_AO @ Wo^T + bo, row-major [B*S, D].
// grid: (DM/TS, (BB*SS)/TS), block: 256
// ---------------------------------------------------------------------------
__global__ __launch_bounds__(256) void oproj_kernel(
    float* __restrict__ out,
    const float* __restrict__ Wo, const float* __restrict__ bo)
{
    __shared__ float As[KC][TS+PAD];
    __shared__ float Bs[KC][TS+PAD];

    int tid = threadIdx.x;
    int tx = tid & 15, ty = tid >> 4;
    int rowBase = blockIdx.y * TS;
    int colBase = blockIdx.x * TS;
    int lrow = tid >> 2, lkq = tid & 3;

    float acc[4][4] = {};

    for (int kc = 0; kc < DM; kc += KC) {
        float4 av  = *(const float4*)(g_AO + (size_t)(rowBase + lrow) * DM + kc + lkq * 4);
        float4 bv4 = *(const float4*)(Wo   + (size_t)(colBase + lrow) * DM + kc + lkq * 4);
        As[lkq*4+0][lrow] = av.x;  As[lkq*4+1][lrow] = av.y;
        As[lkq*4+2][lrow] = av.z;  As[lkq*4+3][lrow] = av.w;
        Bs[lkq*4+0][lrow] = bv4.x; Bs[lkq*4+1][lrow] = bv4.y;
        Bs[lkq*4+2][lrow] = bv4.z; Bs[lkq*4+3][lrow] = bv4.w;
        __syncthreads();

        #pragma unroll
        for (int k = 0; k < KC; k++) {
            float4 a = *(const float4*)&As[k][ty*4];
            float4 b = *(const float4*)&Bs[k][tx*4];
            float ar[4] = {a.x, a.y, a.z, a.w};
            float br[4] = {b.x, b.y, b.z, b.w};
            #pragma unroll
            for (int r = 0; r < 4; r++)
                #pragma unroll
                for (int c = 0; c < 4; c++)
                    acc[r][c] += ar[r] * br[c];
        }
        __syncthreads();
    }

    #pragma unroll
    for (int r = 0; r < 4; r++) {
        int gi = rowBase + ty*4 + r;
        #pragma unroll
        for (int c = 0; c < 4; c++) {
            int gj = colBase + tx*4 + c;
            out[(size_t)gi * DM + gj] = acc[r][c] + bo[gj];
        }
    }
}

// ---------------------------------------------------------------------------
extern "C" void kernel_launch(void* const* d_in, const int* in_sizes, int n_in,
                              void* d_out, int out_size)
{
    (void)in_sizes; (void)n_in; (void)out_size;
    const float* query = (const float*)d_in[0];
    const float* key   = (const float*)d_in[1];
    const float* value = (const float*)d_in[2];
    const float* Wq    = (const float*)d_in[3];
    const float* bq    = (const float*)d_in[4];
    const float* Wk    = (const float*)d_in[5];
    const float* bk    = (const float*)d_in[6];
    const float* Wv    = (const float*)d_in[7];
    const float* bv    = (const float*)d_in[8];
    const float* Wo    = (const float*)d_in[9];
    const float* bo    = (const float*)d_in[10];

    float* out  = (float*)d_out;                       // [B, S, D]
    float* attn = out + (size_t)BB * SS * DM;          // [B, H, S, S]

    dim3 blk(256);
    proj_qkv_kernel<<<dim3(DM/TS, (BB*SS)/TS, 3), blk>>>(
        query, key, value, Wq, bq, Wk, bk, Wv, bv);
    scores_kernel<<<dim3(SS/TS, SS/TS, BH), blk>>>(attn);
    softmax_kernel<<<BH*SS, 256>>>(attn);
    av_kernel<<<dim3(SS/TS, 1, BH), blk>>>(attn);
    oproj_kernel<<<dim3(DM/TS, (BB*SS)/TS), blk>>>(out, Wo, bo);
}

// round 8
// speedup vs baseline: 3.9205x; 3.9205x over previous
#include <cuda_runtime.h>
#include <cuda_bf16.h>
#include <cstdint>
#include <cstddef>

#define BB 4
#define SS 2048
#define DM 1024
#define NH 16
#define DK 64
#define BH (BB*NH)

#define TM 128          // block tile M
#define TN 64           // block tile N
#define KC 32           // K floats per stage
#define LDS_W 20        // smem row stride in u32 (= 40 bf16)

// ---------------- scratch (allocation-free rule) ----------------
__device__ float g_Q [(size_t)BH*SS*DK];   // [bh][s][d]
__device__ float g_K [(size_t)BH*SS*DK];   // [bh][s][d]
__device__ float g_Vt[(size_t)BH*DK*SS];   // [bh][d][s]
__device__ float g_AO[(size_t)BB*SS*DM];   // [b*s][dm]
__device__ float g_rsum[(size_t)BH*SS];    // softmax row sums

// ---------------- helpers ----------------
#define MMA16816(c, a, b) \
  asm volatile("mma.sync.aligned.m16n8k16.row.col.f32.bf16.bf16.f32 " \
    "{%0,%1,%2,%3}, {%4,%5,%6,%7}, {%8,%9}, {%0,%1,%2,%3};" \
    : "+f"((c)[0]), "+f"((c)[1]), "+f"((c)[2]), "+f"((c)[3]) \
    : "r"((a)[0]), "r"((a)[1]), "r"((a)[2]), "r"((a)[3]), "r"((b)[0]), "r"((b)[1]))

static __device__ __forceinline__ unsigned pack2(float lo, float hi){
    __nv_bfloat162 t = __floats2bfloat162_rn(lo, hi);   // .x = lo half (low addr)
    return *reinterpret_cast<unsigned*>(&t);
}

static __device__ __forceinline__ void split_store(
    unsigned* __restrict__ H, unsigned* __restrict__ L, int row, int q, float4 v)
{
    float hx = __bfloat162float(__float2bfloat16_rn(v.x));
    float hy = __bfloat162float(__float2bfloat16_rn(v.y));
    float hz = __bfloat162float(__float2bfloat16_rn(v.z));
    float hw = __bfloat162float(__float2bfloat16_rn(v.w));
    unsigned base = (unsigned)(row*LDS_W + q*2);
    H[base]   = pack2(v.x, v.y);
    H[base+1] = pack2(v.z, v.w);
    L[base]   = pack2(v.x-hx, v.y-hy);
    L[base+1] = pack2(v.z-hz, v.w-hw);
}

// exp via FFMA polynomial (frees the MUFU pipe; rel err ~2e-6, range |x|<~10)
static __device__ __forceinline__ float fast_exp(float x){
    float t = x * 1.4426950408889634f;
    float m = t + 12582912.0f;                       // round-to-nearest-int trick
    int   ii = __float_as_int(m) - 0x4B400000;
    float f  = t - (m - 12582912.0f);
    float p = 0.0013333558f;
    p = fmaf(p, f, 0.0096181291f);
    p = fmaf(p, f, 0.0555041087f);
    p = fmaf(p, f, 0.2402265070f);
    p = fmaf(p, f, 0.6931471806f);
    p = fmaf(p, f, 1.0f);
    return __int_as_float(__float_as_int(p) + (ii << 23));
}

// ---------------------------------------------------------------------------
// bf16x3 tile GEMM: acc[2][4][4] += A[TM x K] * B[TN x K]^T  (fp32 in, fp32 out)
// 256 threads, warp grid 4(m) x 2(n), warp tile 32x32 of m16n8k16 atoms.
// If NORM: A rows scaled by invp[] during load and written back to wbA.
// ---------------------------------------------------------------------------
template<bool NORM>
static __device__ __forceinline__ void run_gemm(
    const float* __restrict__ A, long lda,
    const float* __restrict__ B, long ldb,
    int kTotal, float acc[2][4][4],
    const float* invp, float* wbA,
    unsigned* AsH, unsigned* AsL, unsigned* BsH, unsigned* BsL)
{
    int tid = threadIdx.x;
    int lane = tid & 31, wid = tid >> 5;
    int wm = (wid & 3) * 32, wn = (wid >> 2) * 32;
    int lg = lane >> 2, lt = lane & 3;

    float4 va[4], vb[2];
    int nStages = kTotal / KC;

    #pragma unroll
    for (int i=0;i<4;i++){ int f=i*256+tid; va[i] = *(const float4*)(A + (long)(f>>3)*lda + (f&7)*4); }
    #pragma unroll
    for (int i=0;i<2;i++){ int f=i*256+tid; vb[i] = *(const float4*)(B + (long)(f>>3)*ldb + (f&7)*4); }

    for (int s = 0; s < nStages; s++) {
        int kc = s*KC;
        if (s) __syncthreads();           // previous stage compute done
        #pragma unroll
        for (int i=0;i<4;i++){
            int f=i*256+tid; int row=f>>3, q=f&7;
            float4 v = va[i];
            if (NORM){
                float sc = invp[i];
                v.x*=sc; v.y*=sc; v.z*=sc; v.w*=sc;
                *(float4*)(wbA + (long)row*lda + kc + q*4) = v;
            }
            split_store(AsH, AsL, row, q, v);
        }
        #pragma unroll
        for (int i=0;i<2;i++){
            int f=i*256+tid;
            split_store(BsH, BsL, f>>3, f&7, vb[i]);
        }
        __syncthreads();
        if (s+1 < nStages){
            int kn = kc + KC;
            #pragma unroll
            for (int i=0;i<4;i++){ int f=i*256+tid; va[i] = *(const float4*)(A + (long)(f>>3)*lda + kn + (f&7)*4); }
            #pragma unroll
            for (int i=0;i<2;i++){ int f=i*256+tid; vb[i] = *(const float4*)(B + (long)(f>>3)*ldb + kn + (f&7)*4); }
        }
        #pragma unroll
        for (int kh = 0; kh < 2; kh++){
            unsigned aH[2][4], aL[2][4], bH[4][2], bL[4][2];
            #pragma unroll
            for (int mi=0; mi<2; mi++){
                int r = wm + mi*16 + lg;
                unsigned b0 = (unsigned)(r*LDS_W + kh*8 + lt);
                aH[mi][0]=AsH[b0]; aH[mi][1]=AsH[b0+8*LDS_W]; aH[mi][2]=AsH[b0+4]; aH[mi][3]=AsH[b0+8*LDS_W+4];
                aL[mi][0]=AsL[b0]; aL[mi][1]=AsL[b0+8*LDS_W]; aL[mi][2]=AsL[b0+4]; aL[mi][3]=AsL[b0+8*LDS_W+4];
            }
            #pragma unroll
            for (int ni=0; ni<4; ni++){
                int n = wn + ni*8 + lg;
                unsigned b0 = (unsigned)(n*LDS_W + kh*8 + lt);
                bH[ni][0]=BsH[b0]; bH[ni][1]=BsH[b0+4];
                bL[ni][0]=BsL[b0]; bL[ni][1]=BsL[b0+4];
            }
            #pragma unroll
            for (int mi=0; mi<2; mi++)
                #pragma unroll
                for (int ni=0; ni<4; ni++){
                    MMA16816(acc[mi][ni], aH[mi], bH[ni]);   // hi*hi
                    MMA16816(acc[mi][ni], aL[mi], bH[ni]);   // lo*hi
                    MMA16816(acc[mi][ni], aH[mi], bL[ni]);   // hi*lo
                }
        }
    }
}

#define DECL_SMEM() \
    __shared__ unsigned AsH[TM*LDS_W], AsL[TM*LDS_W]; \
    __shared__ unsigned BsH[TN*LDS_W], BsL[TN*LDS_W]

// ---------------------------------------------------------------------------
__global__ __launch_bounds__(512) void k_zero(){
    int i = blockIdx.x * 512 + threadIdx.x;
    if (i < BH*SS) g_rsum[i] = 0.0f;
}

// K1: QKV projections. z selects Q/K/V; writes Q,K [bh,s,d]; V transposed [bh,d,s].
__global__ __launch_bounds__(256) void k_proj(
    const float* __restrict__ Xq, const float* __restrict__ Xk, const float* __restrict__ Xv,
    const float* __restrict__ Wq, const float* __restrict__ bq,
    const float* __restrict__ Wk, const float* __restrict__ bk,
    const float* __restrict__ Wv, const float* __restrict__ bv)
{
    DECL_SMEM();
    int tid = threadIdx.x;
    int lane = tid & 31, wid = tid >> 5;
    int wm = (wid & 3) * 32, wn = (wid >> 2) * 32;
    int lg = lane >> 2, lt = lane & 3;

    int z = blockIdx.z;
    const float* X    = (z==0) ? Xq : (z==1 ? Xk : Xv);
    const float* W    = (z==0) ? Wq : (z==1 ? Wk : Wv);
    const float* bias = (z==0) ? bq : (z==1 ? bk : bv);
    int rowBase = blockIdx.y * TM;
    int h = blockIdx.x;                  // TN == DK -> n-tile == head

    float acc[2][4][4] = {};
    run_gemm<false>(X + (long)rowBase*DM, DM, W + (long)h*TN*DM, DM, DM,
                    acc, nullptr, nullptr, AsH, AsL, BsH, BsL);

    #pragma unroll
    for (int mi=0; mi<2; mi++)
        #pragma unroll
        for (int half=0; half<2; half++){
            int gi = rowBase + wm + mi*16 + lg + half*8;
            int b = gi >> 11, sI = gi & (SS-1);
            if (z < 2) {
                float* dst = (z==0 ? g_Q : g_K) + ((long)(b*NH + h)*SS + sI)*DK;
                #pragma unroll
                for (int ni=0; ni<4; ni++){
                    int col = wn + ni*8 + lt*2;
                    float2 o = { acc[mi][ni][half*2+0] + bias[h*64 + col],
                                 acc[mi][ni][half*2+1] + bias[h*64 + col + 1] };
                    *(float2*)(dst + col) = o;
                }
            } else {
                float* dst = g_Vt + (long)(b*NH + h)*DK*SS + sI;
                #pragma unroll
                for (int ni=0; ni<4; ni++){
                    int col = wn + ni*8 + lt*2;
                    dst[(long)col*SS]     = acc[mi][ni][half*2+0] + bias[h*64 + col];
                    dst[(long)(col+1)*SS] = acc[mi][ni][half*2+1] + bias[h*64 + col + 1];
                }
            }
        }
}

// K2: scores tile = Q K^T; epilogue writes e = exp(s/8) + atomic row sums.
__global__ __launch_bounds__(256) void k_scores(float* __restrict__ attn)
{
    DECL_SMEM();
    int tid = threadIdx.x;
    int lane = tid & 31, wid = tid >> 5;
    int wm = (wid & 3) * 32, wn = (wid >> 2) * 32;
    int lg = lane >> 2, lt = lane & 3;

    int bh = blockIdx.z;
    int rowBase = blockIdx.y * TM;
    int nb = blockIdx.x * TN;

    float acc[2][4][4] = {};
    run_gemm<false>(g_Q + ((long)bh*SS + rowBase)*DK, DK,
                    g_K + ((long)bh*SS + nb)*DK, DK, DK,
                    acc, nullptr, nullptr, AsH, AsL, BsH, BsL);

    float* base = attn + (long)bh*SS*SS;
    #pragma unroll
    for (int mi=0; mi<2; mi++)
        #pragma unroll
        for (int half=0; half<2; half++){
            int gi = rowBase + wm + mi*16 + lg + half*8;
            float* arow = base + (long)gi*SS + nb + wn;
            float psum = 0.0f;
            #pragma unroll
            for (int ni=0; ni<4; ni++){
                float e0 = fast_exp(acc[mi][ni][half*2+0] * 0.125f);
                float e1 = fast_exp(acc[mi][ni][half*2+1] * 0.125f);
                psum += e0 + e1;
                float2 o = { e0, e1 };
                *(float2*)(arow + ni*8 + lt*2) = o;
            }
            psum += __shfl_xor_sync(0xffffffffu, psum, 1);
            psum += __shfl_xor_sync(0xffffffffu, psum, 2);
            if (lt == 0) atomicAdd(&g_rsum[(long)bh*SS + gi], psum);
        }
}

// K3: normalize e -> p (written back = final attn_weights) fused with O_h = P*V.
__global__ __launch_bounds__(256) void k_av(float* __restrict__ attn)
{
    DECL_SMEM();
    int tid = threadIdx.x;
    int lane = tid & 31, wid = tid >> 5;
    int wm = (wid & 3) * 32, wn = (wid >> 2) * 32;
    int lg = lane >> 2, lt = lane & 3;

    int bh = blockIdx.z;
    int rowBase = blockIdx.y * TM;

    float invp[4];
    #pragma unroll
    for (int i = 0; i < 4; i++)
        invp[i] = 1.0f / g_rsum[(long)bh*SS + rowBase + i*32 + (tid>>3)];

    float* Ap = attn + (long)bh*SS*SS + (long)rowBase*SS;

    float acc[2][4][4] = {};
    run_gemm<true>(Ap, SS, g_Vt + (long)bh*DK*SS, SS, SS,
                   acc, invp, Ap, AsH, AsL, BsH, BsL);

    int b = bh >> 4, h = bh & 15;
    #pragma unroll
    for (int mi=0; mi<2; mi++)
        #pragma unroll
        for (int half=0; half<2; half++){
            int gi = rowBase + wm + mi*16 + lg + half*8;
            float* dst = g_AO + ((long)b*SS + gi)*DM + h*DK;
            #pragma unroll
            for (int ni=0; ni<4; ni++){
                int col = wn + ni*8 + lt*2;
                float2 o = { acc[mi][ni][half*2+0], acc[mi][ni][half*2+1] };
                *(float2*)(dst + col) = o;
            }
        }
}

// K4: output projection out = AO * Wo^T + bo
__global__ __launch_bounds__(256) void k_oproj(
    float* __restrict__ out, const float* __restrict__ Wo, const float* __restrict__ bo)
{
    DECL_SMEM();
    int tid = threadIdx.x;
    int lane = tid & 31, wid = tid >> 5;
    int wm = (wid & 3) * 32, wn = (wid >> 2) * 32;
    int lg = lane >> 2, lt = lane & 3;

    int rowBase = blockIdx.y * TM;
    int nb = blockIdx.x * TN;

    float acc[2][4][4] = {};
    run_gemm<false>(g_AO + (long)rowBase*DM, DM, Wo + (long)nb*DM, DM, DM,
                    acc, nullptr, nullptr, AsH, AsL, BsH, BsL);

    #pragma unroll
    for (int mi=0; mi<2; mi++)
        #pragma unroll
        for (int half=0; half<2; half++){
            int gi = rowBase + wm + mi*16 + lg + half*8;
            float* dst = out + (long)gi*DM + nb;
            #pragma unroll
            for (int ni=0; ni<4; ni++){
                int col = wn + ni*8 + lt*2;
                float2 o = { acc[mi][ni][half*2+0] + bo[nb + col],
                             acc[mi][ni][half*2+1] + bo[nb + col + 1] };
                *(float2*)(dst + col) = o;
            }
        }
}

// ---------------------------------------------------------------------------
extern "C" void kernel_launch(void* const* d_in, const int* in_sizes, int n_in,
                              void* d_out, int out_size)
{
    (void)in_sizes; (void)n_in; (void)out_size;
    const float* query = (const float*)d_in[0];
    const float* key   = (const float*)d_in[1];
    const float* value = (const float*)d_in[2];
    const float* Wq    = (const float*)d_in[3];
    const float* bq    = (const float*)d_in[4];
    const float* Wk    = (const float*)d_in[5];
    const float* bk    = (const float*)d_in[6];
    const float* Wv    = (const float*)d_in[7];
    const float* bv    = (const float*)d_in[8];
    const float* Wo    = (const float*)d_in[9];
    const float* bo    = (const float*)d_in[10];

    float* out  = (float*)d_out;                  // [B, S, D]
    float* attn = out + (size_t)BB*SS*DM;         // [B, H, S, S]

    k_zero<<<(BH*SS + 511)/512, 512>>>();
    k_proj<<<dim3(NH, (BB*SS)/TM, 3), 256>>>(query, key, value, Wq, bq, Wk, bk, Wv, bv);
    k_scores<<<dim3(SS/TN, SS/TM, BH), 256>>>(attn);
    k_av<<<dim3(1, SS/TM, BH), 256>>>(attn);
    k_oproj<<<dim3(DM/TN, (BB*SS)/TM), 256>>>(out, Wo, bo);
}